// round 2
// baseline (speedup 1.0000x reference)
#include <cuda_runtime.h>

// out[m][n] = C[m][n] * D[n];  8192 x 8192 f32, row-major.
// Column-owner layout: each thread owns one float4 column, loads its D scale
// once, and streams ROWS_PER_BLOCK rows. Streaming cache hints (__ldcs/__stcs)
// since C/out have zero reuse. All 32-bit indexing.

static constexpr int NR4            = 2048;   // 8192 floats / 4 per float4
static constexpr int ROWS_PER_BLOCK = 16;
static constexpr int COL_BLOCKS     = NR4 / 256;            // 8
static constexpr int ROW_BLOCKS     = 8192 / ROWS_PER_BLOCK; // 512

__global__ __launch_bounds__(256)
void colscale_kernel(const float4* __restrict__ C,
                     const float4* __restrict__ D,
                     float4* __restrict__ out)
{
    const int col  = blockIdx.x * 256 + threadIdx.x;       // 0..2047
    const int row0 = blockIdx.y * ROWS_PER_BLOCK;

    const float4 d = __ldg(&D[col]);

    int idx = row0 * NR4 + col;   // fits in 31 bits (max 16.7M)

    #pragma unroll
    for (int r = 0; r < ROWS_PER_BLOCK; r += 4) {
        // Front-batched loads (MLP=4)
        float4 c0 = __ldcs(&C[idx + 0 * NR4]);
        float4 c1 = __ldcs(&C[idx + 1 * NR4]);
        float4 c2 = __ldcs(&C[idx + 2 * NR4]);
        float4 c3 = __ldcs(&C[idx + 3 * NR4]);

        float4 o0 = make_float4(c0.x * d.x, c0.y * d.y, c0.z * d.z, c0.w * d.w);
        float4 o1 = make_float4(c1.x * d.x, c1.y * d.y, c1.z * d.z, c1.w * d.w);
        float4 o2 = make_float4(c2.x * d.x, c2.y * d.y, c2.z * d.z, c2.w * d.w);
        float4 o3 = make_float4(c3.x * d.x, c3.y * d.y, c3.z * d.z, c3.w * d.w);

        __stcs(&out[idx + 0 * NR4], o0);
        __stcs(&out[idx + 1 * NR4], o1);
        __stcs(&out[idx + 2 * NR4], o2);
        __stcs(&out[idx + 3 * NR4], o3);

        idx += 4 * NR4;
    }
}

extern "C" void kernel_launch(void* const* d_in, const int* in_sizes, int n_in,
                              void* d_out, int out_size)
{
    const float4* C = (const float4*)d_in[0];
    const float4* D = (const float4*)d_in[1];
    float4* out     = (float4*)d_out;

    dim3 block(256);
    dim3 grid(COL_BLOCKS, ROW_BLOCKS);   // 8 x 512 = 4096 blocks
    colscale_kernel<<<grid, block>>>(C, D, out);
}

// round 3
// speedup vs baseline: 1.0281x; 1.0281x over previous
#include <cuda_runtime.h>

// out[m][n] = C[m][n] * D[n];  8192 x 8192 f32, row-major.
// Single-pass: 16384 blocks x 256 threads x 4 float4 = 16,777,216 float4s.
// Per-thread loads are spaced STRIDE apart (64 MB) -> spreads across all HBM
// channels / both L2 dies (this was R1's winning property).
// STRIDE % 2048 == 0, so all 4 elements share one D scale -> D loaded once.

static constexpr int NR4    = 2048;                 // float4s per row
static constexpr int STRIDE = 16384 * 256;          // grid * block = 2048*2048

__global__ __launch_bounds__(256, 6)
void colscale_kernel(const float4* __restrict__ C,
                     const float4* __restrict__ D,
                     float4* __restrict__ out)
{
    const int i = blockIdx.x * 256 + threadIdx.x;   // 0 .. 4,194,303

    // STRIDE is a multiple of NR4, so column index is invariant across the 4.
    const float4 d = __ldg(&D[i & (NR4 - 1)]);

    const int i0 = i;
    const int i1 = i + STRIDE;
    const int i2 = i + 2 * STRIDE;
    const int i3 = i + 3 * STRIDE;

    // Front-batched loads (MLP=4), far apart in the address space.
    float4 c0 = C[i0];
    float4 c1 = C[i1];
    float4 c2 = C[i2];
    float4 c3 = C[i3];

    c0.x *= d.x; c0.y *= d.y; c0.z *= d.z; c0.w *= d.w;
    c1.x *= d.x; c1.y *= d.y; c1.z *= d.z; c1.w *= d.w;
    c2.x *= d.x; c2.y *= d.y; c2.z *= d.z; c2.w *= d.w;
    c3.x *= d.x; c3.y *= d.y; c3.z *= d.z; c3.w *= d.w;

    out[i0] = c0;
    out[i1] = c1;
    out[i2] = c2;
    out[i3] = c3;
}

extern "C" void kernel_launch(void* const* d_in, const int* in_sizes, int n_in,
                              void* d_out, int out_size)
{
    const float4* C = (const float4*)d_in[0];
    const float4* D = (const float4*)d_in[1];
    float4* out     = (float4*)d_out;

    colscale_kernel<<<16384, 256>>>(C, D, out);
}